// round 3
// baseline (speedup 1.0000x reference)
#include <cuda_runtime.h>
#include <math.h>

#define NCH   256          // channels
#define PLANE 4096         // 64*64
#define W64   64
#define PITCH 76           // smem row pitch (floats): mult of 4 (16B align), 4-row stride != 0 mod 32 banks
#define SROWS 68           // 64 + 2*2 row halo
#define COFF  4            // column halo offset (4 for float4 alignment; window needs >=2)
#define ROFF  2            // row halo offset

__device__ __forceinline__ float4 fmax4(float4 a, float4 b) {
    return make_float4(fmaxf(a.x, b.x), fmaxf(a.y, b.y),
                       fmaxf(a.z, b.z), fmaxf(a.w, b.w));
}

__global__ void __launch_bounds__(256)
spp_kernel(const float* __restrict__ x, float* __restrict__ out) {
    __shared__ float sa[SROWS][PITCH];
    __shared__ float sb[SROWS][PITCH];

    const int tid   = threadIdx.x;
    const int plane = blockIdx.x;          // b*256 + c
    const int batch = plane >> 8;
    const int ch    = plane & 255;

    const float* in = x + (size_t)plane * PLANE;
    float* o0 = out + ((size_t)batch * 4 * NCH + ch) * PLANE;   // group 0 (copy of x)

    // ---- init whole smem buffers to -inf (halos stay -inf forever) ----
    for (int i = tid; i < SROWS * PITCH; i += 256) {
        ((float*)sa)[i] = -INFINITY;
        ((float*)sb)[i] = -INFINITY;
    }
    __syncthreads();

    // ---- load plane (float4, coalesced) + passthrough copy to group 0 ----
    {
        const float4* in4 = (const float4*)in;
        float4*       o4  = (float4*)o0;
        #pragma unroll
        for (int i = tid; i < PLANE / 4; i += 256) {
            float4 v = in4[i];
            int r  = i >> 4;            // 16 float4 per row
            int c4 = (i & 15) << 2;
            *(float4*)&sa[r + ROFF][c4 + COFF] = v;
            o4[i] = v;
        }
    }
    __syncthreads();

    // each thread owns a 4x4 output tile
    const int tr = (tid >> 4) << 2;     // tile row base: 0..60
    const int tc = (tid & 15) << 2;     // tile col base: 0..60

    // three chained window-5 pools: mp5, mp9=mp5^2, mp13=mp5^3
    #pragma unroll
    for (int g = 1; g <= 3; g++) {
        // ---- horizontal window-5 max: sa -> sb ----
        #pragma unroll
        for (int rr = 0; rr < 4; rr++) {
            // padded cols tc..tc+11 == unpadded cols tc-4..tc+7 (need tc-2..tc+5)
            const float4* rp = (const float4*)&sa[tr + rr + ROFF][tc];
            float4 A = rp[0], B = rp[1], Cv = rp[2];
            float v0 = A.z, v1 = A.w, v2 = B.x, v3 = B.y;
            float v4 = B.z, v5 = B.w, v6 = Cv.x, v7 = Cv.y;
            float m12 = fmaxf(v1, v2), m34 = fmaxf(v3, v4), m56 = fmaxf(v5, v6);
            float4 o;
            o.x = fmaxf(v0,  fmaxf(m12, m34));          // max(v0..v4)
            o.y = fmaxf(m12, fmaxf(m34, v5));           // max(v1..v5)
            o.z = fmaxf(fmaxf(v2, m34), m56);           // max(v2..v6)
            o.w = fmaxf(m34, fmaxf(m56, v7));           // max(v3..v7)
            *(float4*)&sb[tr + rr + ROFF][tc + COFF] = o;
        }
        __syncthreads();

        // ---- vertical window-5 max: sb -> sa, write result to out group g ----
        // padded rows tr..tr+7 == unpadded rows tr-2..tr+5
        float4 w0 = *(const float4*)&sb[tr + 0][tc + COFF];
        float4 w1 = *(const float4*)&sb[tr + 1][tc + COFF];
        float4 w2 = *(const float4*)&sb[tr + 2][tc + COFF];
        float4 w3 = *(const float4*)&sb[tr + 3][tc + COFF];
        float4 w4 = *(const float4*)&sb[tr + 4][tc + COFF];
        float4 w5 = *(const float4*)&sb[tr + 5][tc + COFF];
        float4 w6 = *(const float4*)&sb[tr + 6][tc + COFF];
        float4 w7 = *(const float4*)&sb[tr + 7][tc + COFF];

        float4 m12 = fmax4(w1, w2), m34 = fmax4(w3, w4), m56 = fmax4(w5, w6);
        float4 y0 = fmax4(w0,  fmax4(m12, m34));
        float4 y1 = fmax4(m12, fmax4(m34, w5));
        float4 y2 = fmax4(fmax4(w2, m34), m56);
        float4 y3 = fmax4(m34, fmax4(m56, w7));

        *(float4*)&sa[tr + 0 + ROFF][tc + COFF] = y0;
        *(float4*)&sa[tr + 1 + ROFF][tc + COFF] = y1;
        *(float4*)&sa[tr + 2 + ROFF][tc + COFF] = y2;
        *(float4*)&sa[tr + 3 + ROFF][tc + COFF] = y3;

        float4* og4 = (float4*)(o0 + (size_t)g * NCH * PLANE);
        og4[((tr + 0) << 4) + (tc >> 2)] = y0;
        og4[((tr + 1) << 4) + (tc >> 2)] = y1;
        og4[((tr + 2) << 4) + (tc >> 2)] = y2;
        og4[((tr + 3) << 4) + (tc >> 2)] = y3;
        __syncthreads();
    }
}

extern "C" void kernel_launch(void* const* d_in, const int* in_sizes, int n_in,
                              void* d_out, int out_size) {
    const float* x = (const float*)d_in[0];
    float* out = (float*)d_out;
    // 16 batches * 256 channels = 4096 planes
    spp_kernel<<<4096, 256>>>(x, out);
}

// round 4
// speedup vs baseline: 1.2721x; 1.2721x over previous
#include <cuda_runtime.h>
#include <math.h>

#define NCH   256
#define PLANE 4096         // 64*64
#define PITCH 68           // smem row pitch (floats): 16B-aligned, 4-row stride = 272 % 32 = 16 banks (conflict-free)
#define SROWS 68           // 64 rows + 2-row halo top/bottom
#define ROFF  2

__device__ __forceinline__ float4 fmax4(float4 a, float4 b) {
    return make_float4(fmaxf(a.x, b.x), fmaxf(a.y, b.y),
                       fmaxf(a.z, b.z), fmaxf(a.w, b.w));
}

__global__ void __launch_bounds__(256)
spp_kernel(const float* __restrict__ x, float* __restrict__ out) {
    __shared__ float s[SROWS][PITCH];

    const int tid   = threadIdx.x;
    const int plane = blockIdx.x;          // b*256 + c
    const int batch = plane >> 8;
    const int ch    = plane & 255;

    const float* in = x + (size_t)plane * PLANE;
    float* o0 = out + ((size_t)batch * 4 * NCH + ch) * PLANE;   // group 0 (copy of x)

    // ---- init ONLY the row-halo rows (0,1,66,67) to -inf; they are never overwritten ----
    for (int i = tid; i < 2 * PITCH; i += 256) {
        int r = i / PITCH, c = i % PITCH;
        s[r][c]      = -INFINITY;
        s[66 + r][c] = -INFINITY;
    }

    // each thread owns a 4x4 tile
    const int tr = (tid >> 4) << 2;     // tile row base: 0..60
    const int tc = (tid & 15) << 2;     // tile col base: 0..60
    const int ct = tid & 15;            // column tile index (0..15)

    // ---- load own tile (coalesced: 16 consecutive float4 per half-warp) + passthrough copy ----
    float4 v[4];
    {
        const float4* in4 = (const float4*)in;
        float4*       o4  = (float4*)o0;
        #pragma unroll
        for (int rr = 0; rr < 4; rr++) {
            int idx = ((tr + rr) << 4) + (tc >> 2);
            v[rr] = in4[idx];
            o4[idx] = v[rr];
        }
    }
    __syncthreads();   // also covers halo init

    // three chained window-5 pools: mp5, mp9 = mp5^2, mp13 = mp5^3
    #pragma unroll
    for (int g = 1; g <= 3; g++) {
        // ---- horizontal window-5 max, entirely via warp shuffle ----
        float4 h[4];
        #pragma unroll
        for (int rr = 0; rr < 4; rr++) {
            float4 a = v[rr];
            float lz = __shfl_up_sync(0xFFFFFFFFu, a.z, 1);   // col tc-2
            float lw = __shfl_up_sync(0xFFFFFFFFu, a.w, 1);   // col tc-1
            float rx = __shfl_down_sync(0xFFFFFFFFu, a.x, 1); // col tc+4
            float ry = __shfl_down_sync(0xFFFFFFFFu, a.y, 1); // col tc+5
            if (ct == 0)  { lz = -INFINITY; lw = -INFINITY; } // image left border
            if (ct == 15) { rx = -INFINITY; ry = -INFINITY; } // image right border

            float cyz = fmaxf(a.y, a.z);
            float cxw = fmaxf(a.x, a.w);
            float m4  = fmaxf(cyz, cxw);                 // max(x,y,z,w)
            h[rr].x = fmaxf(fmaxf(lz, lw), fmaxf(a.x, cyz));    // cols tc-2..tc+2
            h[rr].y = fmaxf(lw, m4);                            // cols tc-1..tc+3
            h[rr].z = fmaxf(m4, rx);                            // cols tc  ..tc+4
            h[rr].w = fmaxf(cyz, fmaxf(a.w, fmaxf(rx, ry)));    // cols tc+1..tc+5
        }

        // ---- exchange rows through smem for the vertical halo ----
        #pragma unroll
        for (int rr = 0; rr < 4; rr++)
            *(float4*)&s[tr + rr + ROFF][tc] = h[rr];
        __syncthreads();

        // halo rows: tr-2, tr-1, tr+4, tr+5  (padded indices tr+0, tr+1, tr+6, tr+7)
        float4 um2 = *(const float4*)&s[tr + 0][tc];
        float4 um1 = *(const float4*)&s[tr + 1][tc];
        float4 up4 = *(const float4*)&s[tr + 6][tc];
        float4 up5 = *(const float4*)&s[tr + 7][tc];

        // ---- vertical window-5 max in registers ----
        float4 m12 = fmax4(h[1], h[2]);
        float4 m03 = fmax4(h[0], h[3]);
        float4 m4  = fmax4(m12, m03);
        float4 y0 = fmax4(fmax4(um2, um1), fmax4(h[0], m12));
        float4 y1 = fmax4(um1, m4);
        float4 y2 = fmax4(m4, up4);
        float4 y3 = fmax4(m12, fmax4(h[3], fmax4(up4, up5)));

        // ---- store to output group g; keep as input for next pool ----
        float4* og4 = (float4*)(o0 + (size_t)g * NCH * PLANE);
        int base = (tr << 4) + (tc >> 2);
        og4[base +  0] = y0;
        og4[base + 16] = y1;
        og4[base + 32] = y2;
        og4[base + 48] = y3;

        v[0] = y0; v[1] = y1; v[2] = y2; v[3] = y3;

        if (g < 3) __syncthreads();   // protect smem reuse across pools
    }
}

extern "C" void kernel_launch(void* const* d_in, const int* in_sizes, int n_in,
                              void* d_out, int out_size) {
    const float* x = (const float*)d_in[0];
    float* out = (float*)d_out;
    spp_kernel<<<4096, 256>>>(x, out);
}